// round 6
// baseline (speedup 1.0000x reference)
#include <cuda_runtime.h>
#include <cstdint>

#define N_NODES  8000
#define N_EDGES  32000
#define N_GRAPHS 32

// ---------------- scratch (device globals; no allocations anywhere) --------
__device__ float g_h1[N_NODES * 8];
__device__ float g_h2[N_NODES * 64];
__device__ float g_h3[N_NODES * 128];
__device__ float g_agg[N_NODES * 128];
__device__ float g_pool[N_GRAPHS * 128];
// int8 digit fragments of w2 (B matrices), mma.m16n8k32 .col layout.
// index = ((og*IN + i)*2 + chunk)*32 + lane ; .x = b0 reg, .y = b1 reg
__device__ uint2 g_bq1_l3[16 * 64 * 2 * 32];   // digit-1 (high)
__device__ uint2 g_bq0_l3[16 * 64 * 2 * 32];   // digit-0 (low)
__device__ uint2 g_bq1_l2[8 * 8 * 2 * 32];
__device__ uint2 g_bq0_l2[8 * 8 * 2 * 32];
__device__ float g_bs_l3[8192];                 // per-col scale = colmax/16256
__device__ float g_bs_l2[512];

__device__ __forceinline__ float leaky(float v) { return v > 0.f ? v : 0.1f * v; }

__device__ __forceinline__ uint32_t pack8(int x0, int x1, int x2, int x3) {
    return (uint32_t)(x0 & 0xFF) | ((uint32_t)(x1 & 0xFF) << 8) |
           ((uint32_t)(x2 & 0xFF) << 16) | ((uint32_t)(x3 & 0xFF) << 24);
}

// mma.sync m16n8k32 s8 row.col, s32 accumulate in place
__device__ __forceinline__ void imma_acc(int* d, uint32_t a0, uint32_t a1,
                                         uint32_t a2, uint32_t a3,
                                         uint32_t b0, uint32_t b1) {
    asm volatile(
        "mma.sync.aligned.m16n8k32.row.col.s32.s8.s8.s32 "
        "{%0,%1,%2,%3}, {%4,%5,%6,%7}, {%8,%9}, {%0,%1,%2,%3};"
        : "+r"(d[0]), "+r"(d[1]), "+r"(d[2]), "+r"(d[3])
        : "r"(a0), "r"(a1), "r"(a2), "r"(a3), "r"(b0), "r"(b1));
}

// quantize 4 consecutive e values -> packed digit1 / digit0 int8x4
__device__ __forceinline__ void quant4(const float* ep, int kbase, float qs,
                                       uint32_t& hi, uint32_t& lo) {
    int d1[4], d0[4];
#pragma unroll
    for (int j = 0; j < 4; j++) {
        int v  = __float2int_rn(ep[kbase + j] * qs);     // |v| <= 16256
        int v1 = __float2int_rn((float)v * 0.0078125f);  // /128, |v1| <= 127
        d1[j] = v1;
        d0[j] = v - (v1 << 7);                           // |d0| <= 64
    }
    hi = pack8(d1[0], d1[1], d1[2], d1[3]);
    lo = pack8(d0[0], d0[1], d0[2], d0[3]);
}

// ---------------- utility: zero a buffer -----------------------------------
__global__ void zero_kernel(float* __restrict__ p, int n) {
    int i = blockIdx.x * blockDim.x + threadIdx.x;
    if (i < n) p[i] = 0.f;
}

// ---------------- prep: per-column scale of w2 ------------------------------
__global__ void prep_bscale(const float* __restrict__ w2, float* __restrict__ bs,
                            int ncols) {
    int col = blockIdx.x * blockDim.x + threadIdx.x;
    if (col >= ncols) return;
    float m = 0.f;
    for (int k = 0; k < 64; k++) m = fmaxf(m, fabsf(w2[k * ncols + col]));
    bs[col] = m * (1.f / 16256.f);
}

// ---------------- prep: w2 -> int8 digit fragments --------------------------
__global__ void prep_bfrag(const float* __restrict__ w2, const float* __restrict__ bs,
                           uint2* __restrict__ bq1, uint2* __restrict__ bq0,
                           int IN, int OUT, int total) {
    int idx = blockIdx.x * blockDim.x + threadIdx.x;
    if (idx >= total) return;
    int lane  = idx & 31;
    int chunk = (idx >> 5) & 1;
    int i     = (idx >> 6) % IN;
    int og    = idx / (IN * 64);
    int t4 = lane & 3, g = lane >> 2;
    int ncols = IN * OUT;
    int col = i * OUT + og * 8 + g;
    float s  = bs[col];
    float qs = (s > 0.f) ? 1.f / s : 0.f;

    uint32_t h0, l0, h1, l1;
    int d1[4], d0[4];
#pragma unroll
    for (int j = 0; j < 4; j++) {                       // b0 reg: k = chunk*32 + t4*4 + j
        int k = chunk * 32 + t4 * 4 + j;
        int v  = __float2int_rn(w2[k * ncols + col] * qs);
        int v1 = __float2int_rn((float)v * 0.0078125f);
        d1[j] = v1; d0[j] = v - (v1 << 7);
    }
    h0 = pack8(d1[0], d1[1], d1[2], d1[3]);
    l0 = pack8(d0[0], d0[1], d0[2], d0[3]);
#pragma unroll
    for (int j = 0; j < 4; j++) {                       // b1 reg: k += 16
        int k = chunk * 32 + 16 + t4 * 4 + j;
        int v  = __float2int_rn(w2[k * ncols + col] * qs);
        int v1 = __float2int_rn((float)v * 0.0078125f);
        d1[j] = v1; d0[j] = v - (v1 << 7);
    }
    h1 = pack8(d1[0], d1[1], d1[2], d1[3]);
    l1 = pack8(d0[0], d0[1], d0[2], d0[3]);

    bq1[idx] = make_uint2(h0, h1);
    bq0[idx] = make_uint2(l0, l1);
}

// ---------------- fused NNConv via int8 IMMA (layers 2 & 3) -----------------
// Block = 128 edges, 256 threads = 8 warps, 16 edges/warp.
// e (edge hidden, fp32) -> per-row 14-bit fixed point, 2 signed-7b digits.
// D = sA_r*sB_c*(16384*A1B1 + 128*(A1B0+A0B1) + A0B0), exact int32 accum.
template <int IN, int OUT>
__global__ __launch_bounds__(256)
void edge_conv_imma(const float* __restrict__ x,
                    const float* __restrict__ h,
                    const int*   __restrict__ ei,
                    const float* __restrict__ w1,
                    const float* __restrict__ b1,
                    const uint2* __restrict__ bq1,
                    const uint2* __restrict__ bq0,
                    const float* __restrict__ bs,
                    const float* __restrict__ b2,
                    float*       __restrict__ agg)
{
    constexpr int OG = OUT / 8;
    constexpr int W_E    = 0;                    // 128 x 65 fp32
    constexpr int W_H    = W_E + 128 * 65;       // IN x 128
    constexpr int W_B2   = W_H + IN * 128;       // IN*OUT
    constexpr int W_SB   = W_B2 + IN * OUT;      // IN*OUT
    constexpr int W_SA   = W_SB + IN * OUT;      // 128
    constexpr int W_QS   = W_SA + 128;           // 128
    constexpr int W_ATTR = W_QS + 128;           // 384
    constexpr int W_SRC  = W_ATTR + 384;         // 128
    constexpr int W_DST  = W_SRC + 128;          // 128

    extern __shared__ uint32_t sm[];
    float* e_s    = (float*)(sm + W_E);
    float* h_s    = (float*)(sm + W_H);
    float* b2_s   = (float*)(sm + W_B2);
    float* sB_s   = (float*)(sm + W_SB);
    float* sA_s   = (float*)(sm + W_SA);
    float* qs_s   = (float*)(sm + W_QS);
    float* attr_s = (float*)(sm + W_ATTR);
    int*   src_s  = (int*)(sm + W_SRC);
    int*   dst_s  = (int*)(sm + W_DST);

    const int tid = threadIdx.x;
    const int e0  = blockIdx.x * 128;

    // --- edge indices + relative-position attrs
    for (int j = tid; j < 128; j += 256) {
        int s = ei[e0 + j];
        int d = ei[N_EDGES + e0 + j];
        src_s[j] = s; dst_s[j] = d;
        attr_s[j * 3 + 0] = x[d * 4 + 1] - x[s * 4 + 1];
        attr_s[j * 3 + 1] = x[d * 4 + 2] - x[s * 4 + 2];
        attr_s[j * 3 + 2] = x[d * 4 + 3] - x[s * 4 + 3];
    }
    // --- stage b2 and per-col scales
    for (int idx = tid; idx < IN * OUT / 4; idx += 256) {
        ((float4*)b2_s)[idx] = ((const float4*)b2)[idx];
        ((float4*)sB_s)[idx] = ((const float4*)bs)[idx];
    }
    __syncthreads();

    // --- edge hidden e = leaky(attr @ w1 + b1) (fp32, stride-65 rows)
    for (int idx = tid; idx < 128 * 64; idx += 256) {
        int row = idx >> 6, k = idx & 63;
        float a0 = attr_s[row * 3], a1 = attr_s[row * 3 + 1], a2 = attr_s[row * 3 + 2];
        e_s[row * 65 + k] = leaky(b1[k] + a0 * w1[k] + a1 * w1[64 + k] + a2 * w1[128 + k]);
    }
    // --- h[src] gathered transposed: h_s[i*128 + j]
    for (int idx = tid; idx < 128 * (IN / 4); idx += 256) {
        int j = idx & 127, q = idx >> 7;
        float4 v = ((const float4*)(h + src_s[j] * IN))[q];
        h_s[(4 * q + 0) * 128 + j] = v.x;
        h_s[(4 * q + 1) * 128 + j] = v.y;
        h_s[(4 * q + 2) * 128 + j] = v.z;
        h_s[(4 * q + 3) * 128 + j] = v.w;
    }
    __syncthreads();

    // --- per-row scale
    if (tid < 128) {
        float m = 0.f;
        const float* ep = e_s + tid * 65;
#pragma unroll 8
        for (int k = 0; k < 64; k++) m = fmaxf(m, fabsf(ep[k]));
        sA_s[tid] = m * (1.f / 16256.f);
        qs_s[tid] = (m > 0.f) ? 16256.f / m : 0.f;
    }
    __syncthreads();

    const int lane = tid & 31, w = tid >> 5;
    const int g = lane >> 2, t4 = lane & 3;
    const int row0 = w * 16 + g, row1 = row0 + 8;

    // --- A digit fragments in registers (built once)
    const float qs0 = qs_s[row0], qs1 = qs_s[row1];
    const float sA0 = sA_s[row0], sA1 = sA_s[row1];
    const float* ep0 = e_s + row0 * 65;
    const float* ep1 = e_s + row1 * 65;
    uint32_t aH[2][4], aL[2][4];
#pragma unroll
    for (int c = 0; c < 2; c++) {
        int kb = c * 32 + t4 * 4;
        quant4(ep0, kb,      qs0, aH[c][0], aL[c][0]);
        quant4(ep1, kb,      qs1, aH[c][1], aL[c][1]);
        quant4(ep0, kb + 16, qs0, aH[c][2], aL[c][2]);
        quant4(ep1, kb + 16, qs1, aH[c][3], aL[c][3]);
    }

    const int d0n = dst_s[row0], d1n = dst_s[row1];

    for (int og = 0; og < OG; og++) {
        float acc0 = 0.f, acc1 = 0.f, acc2 = 0.f, acc3 = 0.f;
        const uint2* pH = bq1 + (size_t)og * IN * 64 + lane;
        const uint2* pL = bq0 + (size_t)og * IN * 64 + lane;
        const int bcol = og * 8 + t4 * 2;

#pragma unroll 2
        for (int i = 0; i < IN; i++) {
            uint2 B1c0 = pH[(i * 2 + 0) * 32];
            uint2 B1c1 = pH[(i * 2 + 1) * 32];
            uint2 B0c0 = pL[(i * 2 + 0) * 32];
            uint2 B0c1 = pL[(i * 2 + 1) * 32];

            int chh[4] = {0, 0, 0, 0};
            int cx[4]  = {0, 0, 0, 0};
            int cll[4] = {0, 0, 0, 0};
            imma_acc(chh, aH[0][0], aH[0][1], aH[0][2], aH[0][3], B1c0.x, B1c0.y);
            imma_acc(chh, aH[1][0], aH[1][1], aH[1][2], aH[1][3], B1c1.x, B1c1.y);
            imma_acc(cx,  aH[0][0], aH[0][1], aH[0][2], aH[0][3], B0c0.x, B0c0.y);
            imma_acc(cx,  aH[1][0], aH[1][1], aH[1][2], aH[1][3], B0c1.x, B0c1.y);
            imma_acc(cx,  aL[0][0], aL[0][1], aL[0][2], aL[0][3], B1c0.x, B1c0.y);
            imma_acc(cx,  aL[1][0], aL[1][1], aL[1][2], aL[1][3], B1c1.x, B1c1.y);
            imma_acc(cll, aL[0][0], aL[0][1], aL[0][2], aL[0][3], B0c0.x, B0c0.y);
            imma_acc(cll, aL[1][0], aL[1][1], aL[1][2], aL[1][3], B0c1.x, B0c1.y);

            float sb0 = sB_s[i * OUT + bcol];
            float sb1 = sB_s[i * OUT + bcol + 1];
            float bb0 = b2_s[i * OUT + bcol];
            float bb1 = b2_s[i * OUT + bcol + 1];
            float hv0 = h_s[i * 128 + row0];
            float hv1 = h_s[i * 128 + row1];

            float f0 = fmaf(16384.f, (float)chh[0], fmaf(128.f, (float)cx[0], (float)cll[0]));
            float f1 = fmaf(16384.f, (float)chh[1], fmaf(128.f, (float)cx[1], (float)cll[1]));
            float f2 = fmaf(16384.f, (float)chh[2], fmaf(128.f, (float)cx[2], (float)cll[2]));
            float f3 = fmaf(16384.f, (float)chh[3], fmaf(128.f, (float)cx[3], (float)cll[3]));

            float v0 = leaky(fmaf(f0, sA0 * sb0, bb0));
            float v1 = leaky(fmaf(f1, sA0 * sb1, bb1));
            float v2 = leaky(fmaf(f2, sA1 * sb0, bb0));
            float v3 = leaky(fmaf(f3, sA1 * sb1, bb1));
            acc0 += hv0 * v0;
            acc1 += hv0 * v1;
            acc2 += hv1 * v2;
            acc3 += hv1 * v3;
        }
        atomicAdd(&agg[d0n * OUT + bcol    ], acc0);
        atomicAdd(&agg[d0n * OUT + bcol + 1], acc1);
        atomicAdd(&agg[d1n * OUT + bcol    ], acc2);
        atomicAdd(&agg[d1n * OUT + bcol + 1], acc3);
    }
}

// ---------------- fused NNConv edge kernel (fp32, layer 1) ------------------
template <int IN, int OUT, int TILE_E>
__global__ __launch_bounds__(256)
void edge_conv_kernel(const float* __restrict__ x,
                      const float* __restrict__ h,
                      const int*   __restrict__ ei,
                      const float* __restrict__ w1,
                      const float* __restrict__ b1,
                      const float* __restrict__ w2,
                      const float* __restrict__ b2,
                      float*       __restrict__ agg)
{
    constexpr int CT  = OUT / 4;
    constexpr int ET  = 256 / CT;
    constexpr int EPT = TILE_E / ET;

    extern __shared__ float fsmem[];
    float* e_s    = fsmem;
    float* h_s    = e_s + TILE_E * 68;
    float* w2_s   = h_s + TILE_E * IN;
    float* b2_s   = w2_s + 64 * OUT;
    float* attr_s = b2_s + OUT;
    int*   src_s  = (int*)(attr_s + TILE_E * 3);
    int*   dst_s  = src_s + TILE_E;

    const int tid = threadIdx.x;
    const int e0  = blockIdx.x * TILE_E;

    for (int j = tid; j < TILE_E; j += 256) {
        int s = ei[e0 + j];
        int d = ei[N_EDGES + e0 + j];
        src_s[j] = s; dst_s[j] = d;
        attr_s[j * 3 + 0] = x[d * 4 + 1] - x[s * 4 + 1];
        attr_s[j * 3 + 1] = x[d * 4 + 2] - x[s * 4 + 2];
        attr_s[j * 3 + 2] = x[d * 4 + 3] - x[s * 4 + 3];
    }
    __syncthreads();

    for (int idx = tid; idx < TILE_E * (IN / 4); idx += 256) {
        int j = idx / (IN / 4), q = idx % (IN / 4);
        ((float4*)&h_s[j * IN])[q] = ((const float4*)&h[src_s[j] * IN])[q];
    }
    for (int idx = tid; idx < TILE_E * 64; idx += 256) {
        int j = idx >> 6, k = idx & 63;
        float a0 = attr_s[j * 3], a1 = attr_s[j * 3 + 1], a2 = attr_s[j * 3 + 2];
        e_s[j * 68 + k] = leaky(b1[k] + a0 * w1[k] + a1 * w1[64 + k] + a2 * w1[128 + k]);
    }

    const int ce = tid % CT;
    const int te = tid / CT;
    const int c0 = ce * 4;

    float acc[EPT][4];
#pragma unroll
    for (int j = 0; j < EPT; j++) { acc[j][0] = acc[j][1] = acc[j][2] = acc[j][3] = 0.f; }

    for (int i = 0; i < IN; i++) {
        __syncthreads();
        for (int idx = tid * 4; idx < 64 * OUT; idx += 1024) {
            int k = idx / OUT, o = idx % OUT;
            *(float4*)&w2_s[idx] = *(const float4*)&w2[k * (IN * OUT) + i * OUT + o];
        }
        if (tid < OUT) b2_s[tid] = b2[i * OUT + tid];
        __syncthreads();

        float c[EPT][4];
#pragma unroll
        for (int j = 0; j < EPT; j++) {
            c[j][0] = b2_s[c0];     c[j][1] = b2_s[c0 + 1];
            c[j][2] = b2_s[c0 + 2]; c[j][3] = b2_s[c0 + 3];
        }
        for (int k = 0; k < 64; k += 4) {
            float4 w0 = *(const float4*)&w2_s[(k + 0) * OUT + c0];
            float4 wA = *(const float4*)&w2_s[(k + 1) * OUT + c0];
            float4 wB = *(const float4*)&w2_s[(k + 2) * OUT + c0];
            float4 wC = *(const float4*)&w2_s[(k + 3) * OUT + c0];
#pragma unroll
            for (int j = 0; j < EPT; j++) {
                int eg = te + j * ET;
                float4 ev = *(const float4*)&e_s[eg * 68 + k];
                c[j][0] += ev.x * w0.x + ev.y * wA.x + ev.z * wB.x + ev.w * wC.x;
                c[j][1] += ev.x * w0.y + ev.y * wA.y + ev.z * wB.y + ev.w * wC.y;
                c[j][2] += ev.x * w0.z + ev.y * wA.z + ev.z * wB.z + ev.w * wC.z;
                c[j][3] += ev.x * w0.w + ev.y * wA.w + ev.z * wB.w + ev.w * wC.w;
            }
        }
#pragma unroll
        for (int j = 0; j < EPT; j++) {
            int eg = te + j * ET;
            float hv = h_s[eg * IN + i];
            acc[j][0] += hv * leaky(c[j][0]);
            acc[j][1] += hv * leaky(c[j][1]);
            acc[j][2] += hv * leaky(c[j][2]);
            acc[j][3] += hv * leaky(c[j][3]);
        }
    }

#pragma unroll
    for (int j = 0; j < EPT; j++) {
        int eg = te + j * ET;
        int d  = dst_s[eg];
        atomicAdd(&agg[d * OUT + c0 + 0], acc[j][0]);
        atomicAdd(&agg[d * OUT + c0 + 1], acc[j][1]);
        atomicAdd(&agg[d * OUT + c0 + 2], acc[j][2]);
        atomicAdd(&agg[d * OUT + c0 + 3], acc[j][3]);
    }
}

// ---------------- node update: h_next = leaky(agg + h @ root + cb) ---------
__global__ void node_update_kernel(const float* __restrict__ h,
                                   const float* __restrict__ agg,
                                   const float* __restrict__ root,
                                   const float* __restrict__ cb,
                                   float* __restrict__ out,
                                   int IN, int OUT)
{
    int gid = blockIdx.x * blockDim.x + threadIdx.x;
    if (gid >= N_NODES * OUT) return;
    int n = gid / OUT, o = gid % OUT;
    float t = agg[gid] + cb[o];
    for (int i = 0; i < IN; i++) t += h[n * IN + i] * root[i * OUT + o];
    out[gid] = leaky(t);
}

// ---------------- sum-pool over sorted batch_index --------------------------
#define POOL_CHUNK 50
__global__ void pool_kernel(const float* __restrict__ h3,
                            const int*   __restrict__ batch,
                            float*       __restrict__ g)
{
    int o  = threadIdx.x;
    int n0 = blockIdx.x * POOL_CHUNK;
    int n1 = n0 + POOL_CHUNK; if (n1 > N_NODES) n1 = N_NODES;
    float s = 0.f;
    int cur = batch[n0];
    for (int n = n0; n < n1; n++) {
        int b = batch[n];
        if (b != cur) { atomicAdd(&g[cur * 128 + o], s); s = 0.f; cur = b; }
        s += h3[n * 128 + o];
    }
    atomicAdd(&g[cur * 128 + o], s);
}

// ---------------- readout MLP: 128->128->64->1 ------------------------------
__global__ void readout_kernel(const float* __restrict__ g,
                               const float* __restrict__ w1, const float* __restrict__ b1,
                               const float* __restrict__ w2, const float* __restrict__ b2,
                               const float* __restrict__ w3, const float* __restrict__ b3,
                               float* __restrict__ out)
{
    __shared__ float gin[128], g1[128], g2[64];
    int b = blockIdx.x, t = threadIdx.x;
    gin[t] = g[b * 128 + t];
    __syncthreads();
    float s = b1[t];
    for (int i = 0; i < 128; i++) s += gin[i] * w1[i * 128 + t];
    g1[t] = leaky(s);
    __syncthreads();
    if (t < 64) {
        float s2 = b2[t];
        for (int i = 0; i < 128; i++) s2 += g1[i] * w2[i * 64 + t];
        g2[t] = leaky(s2);
    }
    __syncthreads();
    if (t < 64) g1[t] = g2[t] * w3[t];
    __syncthreads();
    if (t == 0) {
        float s3 = b3[0];
        for (int i = 0; i < 64; i++) s3 += g1[i];
        out[b] = s3;
    }
}

// ---------------- launch ----------------------------------------------------
static constexpr int smem_fp32(int IN, int OUT, int TE) {
    return 4 * (TE * 68 + TE * IN + 64 * OUT + OUT + TE * 3) + 8 * TE;
}
static constexpr int smem_imma(int IN, int OUT) {
    return 4 * (128 * 65 + IN * 128 + 2 * IN * OUT + 128 + 128 + 384 + 256);
}

extern "C" void kernel_launch(void* const* d_in, const int* in_sizes, int n_in,
                              void* d_out, int out_size)
{
    const float* x       = (const float*)d_in[0];
    const int*   ei      = (const int*)  d_in[1];
    const int*   batch   = (const int*)  d_in[2];
    const float* en1_w1  = (const float*)d_in[3];
    const float* en1_b1  = (const float*)d_in[4];
    const float* en1_w2  = (const float*)d_in[5];
    const float* en1_b2  = (const float*)d_in[6];
    const float* en2_w1  = (const float*)d_in[7];
    const float* en2_b1  = (const float*)d_in[8];
    const float* en2_w2  = (const float*)d_in[9];
    const float* en2_b2  = (const float*)d_in[10];
    const float* en3_w1  = (const float*)d_in[11];
    const float* en3_b1  = (const float*)d_in[12];
    const float* en3_w2  = (const float*)d_in[13];
    const float* en3_b2  = (const float*)d_in[14];
    const float* root1   = (const float*)d_in[15];
    const float* cb1     = (const float*)d_in[16];
    const float* root2   = (const float*)d_in[17];
    const float* cb2     = (const float*)d_in[18];
    const float* root3   = (const float*)d_in[19];
    const float* cb3     = (const float*)d_in[20];
    const float* fc1_w   = (const float*)d_in[21];
    const float* fc1_b   = (const float*)d_in[22];
    const float* fc2_w   = (const float*)d_in[23];
    const float* fc2_b   = (const float*)d_in[24];
    const float* fc3_w   = (const float*)d_in[25];
    const float* fc3_b   = (const float*)d_in[26];

    float *h1, *h2, *h3, *agg, *gp, *bs3, *bs2;
    uint2 *bq1_3, *bq0_3, *bq1_2, *bq0_2;
    cudaGetSymbolAddress((void**)&h1,    g_h1);
    cudaGetSymbolAddress((void**)&h2,    g_h2);
    cudaGetSymbolAddress((void**)&h3,    g_h3);
    cudaGetSymbolAddress((void**)&agg,   g_agg);
    cudaGetSymbolAddress((void**)&gp,    g_pool);
    cudaGetSymbolAddress((void**)&bs3,   g_bs_l3);
    cudaGetSymbolAddress((void**)&bs2,   g_bs_l2);
    cudaGetSymbolAddress((void**)&bq1_3, g_bq1_l3);
    cudaGetSymbolAddress((void**)&bq0_3, g_bq0_l3);
    cudaGetSymbolAddress((void**)&bq1_2, g_bq1_l2);
    cudaGetSymbolAddress((void**)&bq0_2, g_bq0_l2);

    constexpr int S1  = smem_fp32(4, 8, 128);
    constexpr int SI2 = smem_imma(8, 64);
    constexpr int SI3 = smem_imma(64, 128);
    cudaFuncSetAttribute(edge_conv_imma<64, 128>,
                         cudaFuncAttributeMaxDynamicSharedMemorySize, SI3);
    cudaFuncSetAttribute(edge_conv_imma<8, 64>,
                         cudaFuncAttributeMaxDynamicSharedMemorySize, SI2);

    // ---- prep: quantize w2 of layers 2 & 3 into int8 digit fragments
    prep_bscale<<<(8192 + 255) / 256, 256>>>(en3_w2, bs3, 8192);
    prep_bscale<<<(512 + 255) / 256, 256>>>(en2_w2, bs2, 512);
    prep_bfrag<<<(16 * 64 * 2 * 32 + 255) / 256, 256>>>(en3_w2, bs3, bq1_3, bq0_3, 64, 128, 16 * 64 * 2 * 32);
    prep_bfrag<<<(8 * 8 * 2 * 32 + 255) / 256, 256>>>(en2_w2, bs2, bq1_2, bq0_2, 8, 64, 8 * 8 * 2 * 32);

    // ---- layer 1: in=4, out=8 (fp32)
    zero_kernel<<<(N_NODES * 8 + 255) / 256, 256>>>(agg, N_NODES * 8);
    edge_conv_kernel<4, 8, 128><<<N_EDGES / 128, 256, S1>>>(
        x, x, ei, en1_w1, en1_b1, en1_w2, en1_b2, agg);
    node_update_kernel<<<(N_NODES * 8 + 255) / 256, 256>>>(x, agg, root1, cb1, h1, 4, 8);

    // ---- layer 2: in=8, out=64 (int8 IMMA)
    zero_kernel<<<(N_NODES * 64 + 255) / 256, 256>>>(agg, N_NODES * 64);
    edge_conv_imma<8, 64><<<N_EDGES / 128, 256, SI2>>>(
        x, h1, ei, en2_w1, en2_b1, bq1_2, bq0_2, bs2, en2_b2, agg);
    node_update_kernel<<<(N_NODES * 64 + 255) / 256, 256>>>(h1, agg, root2, cb2, h2, 8, 64);

    // ---- layer 3: in=64, out=128 (int8 IMMA)
    zero_kernel<<<(N_NODES * 128 + 255) / 256, 256>>>(agg, N_NODES * 128);
    edge_conv_imma<64, 128><<<N_EDGES / 128, 256, SI3>>>(
        x, h2, ei, en3_w1, en3_b1, bq1_3, bq0_3, bs3, en3_b2, agg);
    node_update_kernel<<<(N_NODES * 128 + 255) / 256, 256>>>(h2, agg, root3, cb3, h3, 64, 128);

    // ---- pool + readout
    zero_kernel<<<(N_GRAPHS * 128 + 255) / 256, 256>>>(gp, N_GRAPHS * 128);
    pool_kernel<<<(N_NODES + POOL_CHUNK - 1) / POOL_CHUNK, 128>>>(h3, batch, gp);
    readout_kernel<<<N_GRAPHS, 128>>>(gp, fc1_w, fc1_b, fc2_w, fc2_b, fc3_w, fc3_b,
                                      (float*)d_out);
}

// round 7
// speedup vs baseline: 3.8531x; 3.8531x over previous
#include <cuda_runtime.h>
#include <cuda_bf16.h>
#include <cstdint>

#define N_NODES  8000
#define N_EDGES  32000
#define N_GRAPHS 32

// ---------------- scratch (device globals; no allocations anywhere) --------
__device__ float g_h1[N_NODES * 8];
__device__ float g_h2[N_NODES * 64];
__device__ float g_h3[N_NODES * 128];
__device__ float g_agg[N_NODES * 128];
__device__ float g_pool[N_GRAPHS * 128];
// bf16 B-fragments of w2 in mma.m16n8k16 .col layout.
// index = ((og*IN + i)*4 + kt)*32 + lane ; .x = b0 reg, .y = b1 reg
__device__ uint2 g_bf_l3[16 * 64 * 4 * 32];
__device__ uint2 g_bf_l2[8 * 8 * 4 * 32];

__device__ __forceinline__ float leaky(float v) { return v > 0.f ? v : 0.1f * v; }

__device__ __forceinline__ uint32_t pack_bf2(float x, float y) {
    __nv_bfloat16 bx = __float2bfloat16(x);
    __nv_bfloat16 by = __float2bfloat16(y);
    uint16_t ux = *(uint16_t*)&bx, uy = *(uint16_t*)&by;
    return (uint32_t)ux | ((uint32_t)uy << 16);
}

// mma.sync m16n8k16 row.col f32 += bf16*bf16 (accumulate in place)
__device__ __forceinline__ void mma_acc(float* d, const uint32_t* a,
                                        uint32_t b0, uint32_t b1) {
    asm volatile(
        "mma.sync.aligned.m16n8k16.row.col.f32.bf16.bf16.f32 "
        "{%0,%1,%2,%3}, {%4,%5,%6,%7}, {%8,%9}, {%0,%1,%2,%3};"
        : "+f"(d[0]), "+f"(d[1]), "+f"(d[2]), "+f"(d[3])
        : "r"(a[0]), "r"(a[1]), "r"(a[2]), "r"(a[3]), "r"(b0), "r"(b1));
}

// ---------------- utility: zero a buffer -----------------------------------
__global__ void zero_kernel(float* __restrict__ p, int n) {
    int i = blockIdx.x * blockDim.x + threadIdx.x;
    if (i < n) p[i] = 0.f;
}

// ---------------- prep: w2 [64, IN*OUT] -> bf16 B fragments -----------------
// For mma.sync.m16n8k16 .col B: lane = g*4 + t4
//   b0 -> k = kt*16 + t4*2, +1 ; col = g ;  b1 -> k += 8
// global col = i*OUT + og*8 + g
__global__ void prep_w2_frag(const float* __restrict__ w2,
                             uint2* __restrict__ frag,
                             int IN, int OUT, int total)
{
    int idx = blockIdx.x * blockDim.x + threadIdx.x;
    if (idx >= total) return;
    int lane = idx & 31;
    int kt   = (idx >> 5) & 3;
    int i    = (idx >> 7) % IN;
    int og   = idx / (IN * 128);
    int t4 = lane & 3, g = lane >> 2;
    int ncols = IN * OUT;
    int col = i * OUT + og * 8 + g;
    int k0  = kt * 16 + t4 * 2;

    float w00 = w2[(k0    ) * ncols + col];
    float w01 = w2[(k0 + 1) * ncols + col];
    float w10 = w2[(k0 + 8) * ncols + col];
    float w11 = w2[(k0 + 9) * ncols + col];
    frag[idx] = make_uint2(pack_bf2(w00, w01), pack_bf2(w10, w11));
}

// ---------------- fused NNConv via bf16 mma.sync (layers 2 & 3) -------------
// Block = 128 edges, 256 threads = 8 warps, 16 edges/warp.
// Inner loop processes TWO og groups per iteration -> 2 independent MMA
// chains of 4 (breaks the latency chain that bound round 5).
template <int IN, int OUT>
__global__ __launch_bounds__(256)
void edge_conv_mma(const float* __restrict__ x,
                   const float* __restrict__ h,
                   const int*   __restrict__ ei,
                   const float* __restrict__ w1,
                   const float* __restrict__ b1,
                   const uint2* __restrict__ bfrag,
                   const float* __restrict__ b2,
                   float*       __restrict__ agg)
{
    constexpr int OG = OUT / 8;
    constexpr int W_EHI  = 0;                    // 128 x 33 bf16x2 words
    constexpr int W_H    = W_EHI + 128 * 33;     // IN x 128 fp32
    constexpr int W_B2   = W_H + IN * 128;       // IN*OUT fp32
    constexpr int W_ATTR = W_B2 + IN * OUT;      // 384
    constexpr int W_SRC  = W_ATTR + 384;
    constexpr int W_DST  = W_SRC + 128;

    extern __shared__ uint32_t sm[];
    uint32_t* e_hi   = sm + W_EHI;
    float*    h_s    = (float*)(sm + W_H);
    float*    b2_s   = (float*)(sm + W_B2);
    float*    attr_s = (float*)(sm + W_ATTR);
    int*      src_s  = (int*)(sm + W_SRC);
    int*      dst_s  = (int*)(sm + W_DST);

    const int tid = threadIdx.x;
    const int e0  = blockIdx.x * 128;

    // --- edge indices + relative-position attrs
    for (int j = tid; j < 128; j += 256) {
        int s = ei[e0 + j];
        int d = ei[N_EDGES + e0 + j];
        src_s[j] = s; dst_s[j] = d;
        attr_s[j * 3 + 0] = x[d * 4 + 1] - x[s * 4 + 1];
        attr_s[j * 3 + 1] = x[d * 4 + 2] - x[s * 4 + 2];
        attr_s[j * 3 + 2] = x[d * 4 + 3] - x[s * 4 + 3];
    }
    // --- stage b2
    for (int idx = tid; idx < IN * OUT / 4; idx += 256)
        ((float4*)b2_s)[idx] = ((const float4*)b2)[idx];
    __syncthreads();

    // --- edge hidden e = leaky(attr @ w1 + b1), packed bf16x2
    for (int idx = tid; idx < 4096; idx += 256) {
        int row = idx >> 5, cp = idx & 31;
        float a0 = attr_s[row * 3], a1 = attr_s[row * 3 + 1], a2 = attr_s[row * 3 + 2];
        int c0 = cp * 2, c1 = c0 + 1;
        float v0 = leaky(b1[c0] + a0 * w1[c0] + a1 * w1[64 + c0] + a2 * w1[128 + c0]);
        float v1 = leaky(b1[c1] + a0 * w1[c1] + a1 * w1[64 + c1] + a2 * w1[128 + c1]);
        e_hi[row * 33 + cp] = pack_bf2(v0, v1);
    }
    // --- h[src] gathered transposed: h_s[i*128 + j]
    for (int idx = tid; idx < 128 * (IN / 4); idx += 256) {
        int j = idx & 127, q = idx >> 7;
        float4 v = ((const float4*)(h + src_s[j] * IN))[q];
        h_s[(4 * q + 0) * 128 + j] = v.x;
        h_s[(4 * q + 1) * 128 + j] = v.y;
        h_s[(4 * q + 2) * 128 + j] = v.z;
        h_s[(4 * q + 3) * 128 + j] = v.w;
    }
    __syncthreads();

    const int lane = tid & 31, w = tid >> 5;
    const int g = lane >> 2, t4 = lane & 3;
    const int row0 = w * 16 + g, row1 = row0 + 8;

    // --- A fragments in registers (built once, reused for all tiles)
    uint32_t aF[4][4];
#pragma unroll
    for (int kt = 0; kt < 4; kt++) {
        int cp = kt * 8 + t4;
        aF[kt][0] = e_hi[row0 * 33 + cp];
        aF[kt][1] = e_hi[row1 * 33 + cp];
        aF[kt][2] = e_hi[row0 * 33 + cp + 4];
        aF[kt][3] = e_hi[row1 * 33 + cp + 4];
    }

    const int d0n = dst_s[row0], d1n = dst_s[row1];

    for (int og2 = 0; og2 < OG / 2; og2++) {
        const int ogA = og2 * 2, ogB = ogA + 1;
        const uint2* pA = bfrag + (size_t)ogA * IN * 4 * 32 + lane;
        const uint2* pB = bfrag + (size_t)ogB * IN * 4 * 32 + lane;
        const int bcA = ogA * 8 + t4 * 2;
        const int bcB = ogB * 8 + t4 * 2;

        float accA0 = 0.f, accA1 = 0.f, accA2 = 0.f, accA3 = 0.f;
        float accB0 = 0.f, accB1 = 0.f, accB2 = 0.f, accB3 = 0.f;

#pragma unroll 2
        for (int i = 0; i < IN; i++) {
            uint2 bA[4], bB[4];
#pragma unroll
            for (int kt = 0; kt < 4; kt++) {
                bA[kt] = pA[(i * 4 + kt) * 32];
                bB[kt] = pB[(i * 4 + kt) * 32];
            }
            float dA[4] = {0.f, 0.f, 0.f, 0.f};
            float dB[4] = {0.f, 0.f, 0.f, 0.f};
#pragma unroll
            for (int kt = 0; kt < 4; kt++) {
                mma_acc(dA, aF[kt], bA[kt].x, bA[kt].y);
                mma_acc(dB, aF[kt], bB[kt].x, bB[kt].y);
            }
            float hv0 = h_s[i * 128 + row0];
            float hv1 = h_s[i * 128 + row1];
            float bbA0 = b2_s[i * OUT + bcA], bbA1 = b2_s[i * OUT + bcA + 1];
            float bbB0 = b2_s[i * OUT + bcB], bbB1 = b2_s[i * OUT + bcB + 1];

            accA0 += hv0 * leaky(dA[0] + bbA0);
            accA1 += hv0 * leaky(dA[1] + bbA1);
            accA2 += hv1 * leaky(dA[2] + bbA0);
            accA3 += hv1 * leaky(dA[3] + bbA1);
            accB0 += hv0 * leaky(dB[0] + bbB0);
            accB1 += hv0 * leaky(dB[1] + bbB1);
            accB2 += hv1 * leaky(dB[2] + bbB0);
            accB3 += hv1 * leaky(dB[3] + bbB1);
        }
        atomicAdd(&agg[d0n * OUT + bcA    ], accA0);
        atomicAdd(&agg[d0n * OUT + bcA + 1], accA1);
        atomicAdd(&agg[d1n * OUT + bcA    ], accA2);
        atomicAdd(&agg[d1n * OUT + bcA + 1], accA3);
        atomicAdd(&agg[d0n * OUT + bcB    ], accB0);
        atomicAdd(&agg[d0n * OUT + bcB + 1], accB1);
        atomicAdd(&agg[d1n * OUT + bcB    ], accB2);
        atomicAdd(&agg[d1n * OUT + bcB + 1], accB3);
    }
}

// ---------------- fused NNConv edge kernel (fp32, layer 1) ------------------
template <int IN, int OUT, int TILE_E>
__global__ __launch_bounds__(256)
void edge_conv_kernel(const float* __restrict__ x,
                      const float* __restrict__ h,
                      const int*   __restrict__ ei,
                      const float* __restrict__ w1,
                      const float* __restrict__ b1,
                      const float* __restrict__ w2,
                      const float* __restrict__ b2,
                      float*       __restrict__ agg)
{
    constexpr int CT  = OUT / 4;
    constexpr int ET  = 256 / CT;
    constexpr int EPT = TILE_E / ET;

    extern __shared__ float fsmem[];
    float* e_s    = fsmem;
    float* h_s    = e_s + TILE_E * 68;
    float* w2_s   = h_s + TILE_E * IN;
    float* b2_s   = w2_s + 64 * OUT;
    float* attr_s = b2_s + OUT;
    int*   src_s  = (int*)(attr_s + TILE_E * 3);
    int*   dst_s  = src_s + TILE_E;

    const int tid = threadIdx.x;
    const int e0  = blockIdx.x * TILE_E;

    for (int j = tid; j < TILE_E; j += 256) {
        int s = ei[e0 + j];
        int d = ei[N_EDGES + e0 + j];
        src_s[j] = s; dst_s[j] = d;
        attr_s[j * 3 + 0] = x[d * 4 + 1] - x[s * 4 + 1];
        attr_s[j * 3 + 1] = x[d * 4 + 2] - x[s * 4 + 2];
        attr_s[j * 3 + 2] = x[d * 4 + 3] - x[s * 4 + 3];
    }
    __syncthreads();

    for (int idx = tid; idx < TILE_E * (IN / 4); idx += 256) {
        int j = idx / (IN / 4), q = idx % (IN / 4);
        ((float4*)&h_s[j * IN])[q] = ((const float4*)&h[src_s[j] * IN])[q];
    }
    for (int idx = tid; idx < TILE_E * 64; idx += 256) {
        int j = idx >> 6, k = idx & 63;
        float a0 = attr_s[j * 3], a1 = attr_s[j * 3 + 1], a2 = attr_s[j * 3 + 2];
        e_s[j * 68 + k] = leaky(b1[k] + a0 * w1[k] + a1 * w1[64 + k] + a2 * w1[128 + k]);
    }

    const int ce = tid % CT;
    const int te = tid / CT;
    const int c0 = ce * 4;

    float acc[EPT][4];
#pragma unroll
    for (int j = 0; j < EPT; j++) { acc[j][0] = acc[j][1] = acc[j][2] = acc[j][3] = 0.f; }

    for (int i = 0; i < IN; i++) {
        __syncthreads();
        for (int idx = tid * 4; idx < 64 * OUT; idx += 1024) {
            int k = idx / OUT, o = idx % OUT;
            *(float4*)&w2_s[idx] = *(const float4*)&w2[k * (IN * OUT) + i * OUT + o];
        }
        if (tid < OUT) b2_s[tid] = b2[i * OUT + tid];
        __syncthreads();

        float c[EPT][4];
#pragma unroll
        for (int j = 0; j < EPT; j++) {
            c[j][0] = b2_s[c0];     c[j][1] = b2_s[c0 + 1];
            c[j][2] = b2_s[c0 + 2]; c[j][3] = b2_s[c0 + 3];
        }
        for (int k = 0; k < 64; k += 4) {
            float4 w0 = *(const float4*)&w2_s[(k + 0) * OUT + c0];
            float4 wA = *(const float4*)&w2_s[(k + 1) * OUT + c0];
            float4 wB = *(const float4*)&w2_s[(k + 2) * OUT + c0];
            float4 wC = *(const float4*)&w2_s[(k + 3) * OUT + c0];
#pragma unroll
            for (int j = 0; j < EPT; j++) {
                int eg = te + j * ET;
                float4 ev = *(const float4*)&e_s[eg * 68 + k];
                c[j][0] += ev.x * w0.x + ev.y * wA.x + ev.z * wB.x + ev.w * wC.x;
                c[j][1] += ev.x * w0.y + ev.y * wA.y + ev.z * wB.y + ev.w * wC.y;
                c[j][2] += ev.x * w0.z + ev.y * wA.z + ev.z * wB.z + ev.w * wC.z;
                c[j][3] += ev.x * w0.w + ev.y * wA.w + ev.z * wB.w + ev.w * wC.w;
            }
        }
#pragma unroll
        for (int j = 0; j < EPT; j++) {
            int eg = te + j * ET;
            float hv = h_s[eg * IN + i];
            acc[j][0] += hv * leaky(c[j][0]);
            acc[j][1] += hv * leaky(c[j][1]);
            acc[j][2] += hv * leaky(c[j][2]);
            acc[j][3] += hv * leaky(c[j][3]);
        }
    }

#pragma unroll
    for (int j = 0; j < EPT; j++) {
        int eg = te + j * ET;
        int d  = dst_s[eg];
        atomicAdd(&agg[d * OUT + c0 + 0], acc[j][0]);
        atomicAdd(&agg[d * OUT + c0 + 1], acc[j][1]);
        atomicAdd(&agg[d * OUT + c0 + 2], acc[j][2]);
        atomicAdd(&agg[d * OUT + c0 + 3], acc[j][3]);
    }
}

// ---------------- node update: h_next = leaky(agg + h @ root + cb) ---------
__global__ void node_update_kernel(const float* __restrict__ h,
                                   const float* __restrict__ agg,
                                   const float* __restrict__ root,
                                   const float* __restrict__ cb,
                                   float* __restrict__ out,
                                   int IN, int OUT)
{
    int gid = blockIdx.x * blockDim.x + threadIdx.x;
    if (gid >= N_NODES * OUT) return;
    int n = gid / OUT, o = gid % OUT;
    float t = agg[gid] + cb[o];
    for (int i = 0; i < IN; i++) t += h[n * IN + i] * root[i * OUT + o];
    out[gid] = leaky(t);
}

// ---------------- sum-pool over sorted batch_index --------------------------
#define POOL_CHUNK 50
__global__ void pool_kernel(const float* __restrict__ h3,
                            const int*   __restrict__ batch,
                            float*       __restrict__ g)
{
    int o  = threadIdx.x;
    int n0 = blockIdx.x * POOL_CHUNK;
    int n1 = n0 + POOL_CHUNK; if (n1 > N_NODES) n1 = N_NODES;
    float s = 0.f;
    int cur = batch[n0];
    for (int n = n0; n < n1; n++) {
        int b = batch[n];
        if (b != cur) { atomicAdd(&g[cur * 128 + o], s); s = 0.f; cur = b; }
        s += h3[n * 128 + o];
    }
    atomicAdd(&g[cur * 128 + o], s);
}

// ---------------- readout MLP: 128->128->64->1 ------------------------------
__global__ void readout_kernel(const float* __restrict__ g,
                               const float* __restrict__ w1, const float* __restrict__ b1,
                               const float* __restrict__ w2, const float* __restrict__ b2,
                               const float* __restrict__ w3, const float* __restrict__ b3,
                               float* __restrict__ out)
{
    __shared__ float gin[128], g1[128], g2[64];
    int b = blockIdx.x, t = threadIdx.x;
    gin[t] = g[b * 128 + t];
    __syncthreads();
    float s = b1[t];
    for (int i = 0; i < 128; i++) s += gin[i] * w1[i * 128 + t];
    g1[t] = leaky(s);
    __syncthreads();
    if (t < 64) {
        float s2 = b2[t];
        for (int i = 0; i < 128; i++) s2 += g1[i] * w2[i * 64 + t];
        g2[t] = leaky(s2);
    }
    __syncthreads();
    if (t < 64) g1[t] = g2[t] * w3[t];
    __syncthreads();
    if (t == 0) {
        float s3 = b3[0];
        for (int i = 0; i < 64; i++) s3 += g1[i];
        out[b] = s3;
    }
}

// ---------------- launch ----------------------------------------------------
static constexpr int smem_fp32(int IN, int OUT, int TE) {
    return 4 * (TE * 68 + TE * IN + 64 * OUT + OUT + TE * 3) + 8 * TE;
}
static constexpr int smem_mma(int IN, int OUT) {
    return 4 * (128 * 33 + IN * 128 + IN * OUT + 384 + 256);
}

extern "C" void kernel_launch(void* const* d_in, const int* in_sizes, int n_in,
                              void* d_out, int out_size)
{
    const float* x       = (const float*)d_in[0];
    const int*   ei      = (const int*)  d_in[1];
    const int*   batch   = (const int*)  d_in[2];
    const float* en1_w1  = (const float*)d_in[3];
    const float* en1_b1  = (const float*)d_in[4];
    const float* en1_w2  = (const float*)d_in[5];
    const float* en1_b2  = (const float*)d_in[6];
    const float* en2_w1  = (const float*)d_in[7];
    const float* en2_b1  = (const float*)d_in[8];
    const float* en2_w2  = (const float*)d_in[9];
    const float* en2_b2  = (const float*)d_in[10];
    const float* en3_w1  = (const float*)d_in[11];
    const float* en3_b1  = (const float*)d_in[12];
    const float* en3_w2  = (const float*)d_in[13];
    const float* en3_b2  = (const float*)d_in[14];
    const float* root1   = (const float*)d_in[15];
    const float* cb1     = (const float*)d_in[16];
    const float* root2   = (const float*)d_in[17];
    const float* cb2     = (const float*)d_in[18];
    const float* root3   = (const float*)d_in[19];
    const float* cb3     = (const float*)d_in[20];
    const float* fc1_w   = (const float*)d_in[21];
    const float* fc1_b   = (const float*)d_in[22];
    const float* fc2_w   = (const float*)d_in[23];
    const float* fc2_b   = (const float*)d_in[24];
    const float* fc3_w   = (const float*)d_in[25];
    const float* fc3_b   = (const float*)d_in[26];

    float *h1, *h2, *h3, *agg, *gp;
    uint2 *bf3, *bf2;
    cudaGetSymbolAddress((void**)&h1,  g_h1);
    cudaGetSymbolAddress((void**)&h2,  g_h2);
    cudaGetSymbolAddress((void**)&h3,  g_h3);
    cudaGetSymbolAddress((void**)&agg, g_agg);
    cudaGetSymbolAddress((void**)&gp,  g_pool);
    cudaGetSymbolAddress((void**)&bf3, g_bf_l3);
    cudaGetSymbolAddress((void**)&bf2, g_bf_l2);

    constexpr int S1  = smem_fp32(4, 8, 128);
    constexpr int SM2 = smem_mma(8, 64);
    constexpr int SM3 = smem_mma(64, 128);
    cudaFuncSetAttribute(edge_conv_mma<64, 128>,
                         cudaFuncAttributeMaxDynamicSharedMemorySize, SM3);
    cudaFuncSetAttribute(edge_conv_mma<8, 64>,
                         cudaFuncAttributeMaxDynamicSharedMemorySize, SM2);

    // ---- prep: rearrange w2 of layers 2 & 3 into bf16 mma fragments
    prep_w2_frag<<<(16 * 64 * 4 * 32 + 255) / 256, 256>>>(en3_w2, bf3, 64, 128, 16 * 64 * 4 * 32);
    prep_w2_frag<<<(8 * 8 * 4 * 32 + 255) / 256, 256>>>(en2_w2, bf2, 8, 64, 8 * 8 * 4 * 32);

    // ---- layer 1: in=4, out=8 (fp32)
    zero_kernel<<<(N_NODES * 8 + 255) / 256, 256>>>(agg, N_NODES * 8);
    edge_conv_kernel<4, 8, 128><<<N_EDGES / 128, 256, S1>>>(
        x, x, ei, en1_w1, en1_b1, en1_w2, en1_b2, agg);
    node_update_kernel<<<(N_NODES * 8 + 255) / 256, 256>>>(x, agg, root1, cb1, h1, 4, 8);

    // ---- layer 2: in=8, out=64 (bf16 mma)
    zero_kernel<<<(N_NODES * 64 + 255) / 256, 256>>>(agg, N_NODES * 64);
    edge_conv_mma<8, 64><<<N_EDGES / 128, 256, SM2>>>(
        x, h1, ei, en2_w1, en2_b1, bf2, en2_b2, agg);
    node_update_kernel<<<(N_NODES * 64 + 255) / 256, 256>>>(h1, agg, root2, cb2, h2, 8, 64);

    // ---- layer 3: in=64, out=128 (bf16 mma)
    zero_kernel<<<(N_NODES * 128 + 255) / 256, 256>>>(agg, N_NODES * 128);
    edge_conv_mma<64, 128><<<N_EDGES / 128, 256, SM3>>>(
        x, h2, ei, en3_w1, en3_b1, bf3, en3_b2, agg);
    node_update_kernel<<<(N_NODES * 128 + 255) / 256, 256>>>(h2, agg, root3, cb3, h3, 64, 128);

    // ---- pool + readout
    zero_kernel<<<(N_GRAPHS * 128 + 255) / 256, 256>>>(gp, N_GRAPHS * 128);
    pool_kernel<<<(N_NODES + POOL_CHUNK - 1) / POOL_CHUNK, 128>>>(h3, batch, gp);
    readout_kernel<<<N_GRAPHS, 128>>>(gp, fc1_w, fc1_b, fc2_w, fc2_b, fc3_w, fc3_b,
                                      (float*)d_out);
}

// round 8
// speedup vs baseline: 5.0376x; 1.3074x over previous
#include <cuda_runtime.h>
#include <cuda_bf16.h>
#include <cstdint>

#define N_NODES  8000
#define N_EDGES  32000
#define N_GRAPHS 32

// ---------------- scratch (device globals; no allocations anywhere) --------
__device__ float g_h1[N_NODES * 8];
__device__ float g_h2[N_NODES * 64];
__device__ float g_h3[N_NODES * 128];
__device__ float g_agg[N_NODES * 128];
__device__ float g_pool[N_GRAPHS * 128];
// bf16 B-fragments of w2, per-lane contiguous layout:
// uint4 index = ((og*IN + i)*32 + lane)*2 + q
//   q=0: {kt0.b0, kt0.b1, kt1.b0, kt1.b1}, q=1: {kt2.., kt3..}
__device__ uint4 g_bf_l3[16 * 64 * 32 * 2];
__device__ uint4 g_bf_l2[8 * 8 * 32 * 2];

__device__ __forceinline__ float leaky(float v) { return v > 0.f ? v : 0.1f * v; }

__device__ __forceinline__ uint32_t pack_bf2(float x, float y) {
    __nv_bfloat16 bx = __float2bfloat16(x);
    __nv_bfloat16 by = __float2bfloat16(y);
    uint16_t ux = *(uint16_t*)&bx, uy = *(uint16_t*)&by;
    return (uint32_t)ux | ((uint32_t)uy << 16);
}

// mma.sync m16n8k16 row.col f32 += bf16*bf16 (accumulate in place)
__device__ __forceinline__ void mma_acc(float* d, const uint32_t* a,
                                        uint32_t b0, uint32_t b1) {
    asm volatile(
        "mma.sync.aligned.m16n8k16.row.col.f32.bf16.bf16.f32 "
        "{%0,%1,%2,%3}, {%4,%5,%6,%7}, {%8,%9}, {%0,%1,%2,%3};"
        : "+f"(d[0]), "+f"(d[1]), "+f"(d[2]), "+f"(d[3])
        : "r"(a[0]), "r"(a[1]), "r"(a[2]), "r"(a[3]), "r"(b0), "r"(b1));
}

// ---------------- utility: zero a buffer -----------------------------------
__global__ void zero_kernel(float* __restrict__ p, int n) {
    int i = blockIdx.x * blockDim.x + threadIdx.x;
    if (i < n) p[i] = 0.f;
}

// ---------------- prep: w2 [64, IN*OUT] -> bf16 B fragments -----------------
// Each thread emits ONE uint4 (two kt groups for one lane of one (og,i)).
__global__ void prep_w2_frag(const float* __restrict__ w2,
                             uint4* __restrict__ frag,
                             int IN, int OUT, int total)
{
    int idx = blockIdx.x * blockDim.x + threadIdx.x;
    if (idx >= total) return;
    int q    = idx & 1;
    int lane = (idx >> 1) & 31;
    int i    = (idx >> 6) % IN;
    int og   = idx / (IN * 64);
    int t4 = lane & 3, g = lane >> 2;
    int ncols = IN * OUT;
    int col = i * OUT + og * 8 + g;

    uint32_t r[4];
#pragma unroll
    for (int kk = 0; kk < 2; kk++) {
        int kt = q * 2 + kk;
        int k0 = kt * 16 + t4 * 2;
        r[kk * 2 + 0] = pack_bf2(w2[(k0    ) * ncols + col], w2[(k0 + 1) * ncols + col]);
        r[kk * 2 + 1] = pack_bf2(w2[(k0 + 8) * ncols + col], w2[(k0 + 9) * ncols + col]);
    }
    frag[idx] = make_uint4(r[0], r[1], r[2], r[3]);
}

// ---------------- fused NNConv via bf16 mma.sync (layers 2 & 3) -------------
// Block = 128 edges, 256 threads = 8 warps, 16 edges/warp.
// Two og groups per outer iteration (2 independent MMA chains of 4);
// B fragments software-pipelined (prefetch i+1 during i's MMAs).
template <int IN, int OUT>
__global__ __launch_bounds__(256)
void edge_conv_mma(const float* __restrict__ x,
                   const float* __restrict__ h,
                   const int*   __restrict__ ei,
                   const float* __restrict__ w1,
                   const float* __restrict__ b1,
                   const uint4* __restrict__ bfrag,
                   const float* __restrict__ b2,
                   float*       __restrict__ agg)
{
    constexpr int OG = OUT / 8;
    constexpr int W_EHI  = 0;                    // 128 x 33 bf16x2 words
    constexpr int W_H    = W_EHI + 128 * 33;     // IN x 128 fp32
    constexpr int W_B2   = W_H + IN * 128;       // IN*OUT fp32
    constexpr int W_ATTR = W_B2 + IN * OUT;      // 384
    constexpr int W_SRC  = W_ATTR + 384;
    constexpr int W_DST  = W_SRC + 128;

    extern __shared__ uint32_t sm[];
    uint32_t* e_hi   = sm + W_EHI;
    float*    h_s    = (float*)(sm + W_H);
    float*    b2_s   = (float*)(sm + W_B2);
    float*    attr_s = (float*)(sm + W_ATTR);
    int*      src_s  = (int*)(sm + W_SRC);
    int*      dst_s  = (int*)(sm + W_DST);

    const int tid = threadIdx.x;
    const int e0  = blockIdx.x * 128;

    // --- edge indices + relative-position attrs
    for (int j = tid; j < 128; j += 256) {
        int s = ei[e0 + j];
        int d = ei[N_EDGES + e0 + j];
        src_s[j] = s; dst_s[j] = d;
        attr_s[j * 3 + 0] = x[d * 4 + 1] - x[s * 4 + 1];
        attr_s[j * 3 + 1] = x[d * 4 + 2] - x[s * 4 + 2];
        attr_s[j * 3 + 2] = x[d * 4 + 3] - x[s * 4 + 3];
    }
    // --- stage b2
    for (int idx = tid; idx < IN * OUT / 4; idx += 256)
        ((float4*)b2_s)[idx] = ((const float4*)b2)[idx];
    __syncthreads();

    // --- edge hidden e = leaky(attr @ w1 + b1), packed bf16x2
    for (int idx = tid; idx < 4096; idx += 256) {
        int row = idx >> 5, cp = idx & 31;
        float a0 = attr_s[row * 3], a1 = attr_s[row * 3 + 1], a2 = attr_s[row * 3 + 2];
        int c0 = cp * 2, c1 = c0 + 1;
        float v0 = leaky(b1[c0] + a0 * w1[c0] + a1 * w1[64 + c0] + a2 * w1[128 + c0]);
        float v1 = leaky(b1[c1] + a0 * w1[c1] + a1 * w1[64 + c1] + a2 * w1[128 + c1]);
        e_hi[row * 33 + cp] = pack_bf2(v0, v1);
    }
    // --- h[src] gathered transposed: h_s[i*128 + j]
    for (int idx = tid; idx < 128 * (IN / 4); idx += 256) {
        int j = idx & 127, q = idx >> 7;
        float4 v = ((const float4*)(h + src_s[j] * IN))[q];
        h_s[(4 * q + 0) * 128 + j] = v.x;
        h_s[(4 * q + 1) * 128 + j] = v.y;
        h_s[(4 * q + 2) * 128 + j] = v.z;
        h_s[(4 * q + 3) * 128 + j] = v.w;
    }
    __syncthreads();

    const int lane = tid & 31, w = tid >> 5;
    const int g = lane >> 2, t4 = lane & 3;
    const int row0 = w * 16 + g, row1 = row0 + 8;

    // --- A fragments in registers (built once, reused for all tiles)
    uint32_t aF[4][4];
#pragma unroll
    for (int kt = 0; kt < 4; kt++) {
        int cp = kt * 8 + t4;
        aF[kt][0] = e_hi[row0 * 33 + cp];
        aF[kt][1] = e_hi[row1 * 33 + cp];
        aF[kt][2] = e_hi[row0 * 33 + cp + 4];
        aF[kt][3] = e_hi[row1 * 33 + cp + 4];
    }

    const int d0n = dst_s[row0], d1n = dst_s[row1];

    for (int og2 = 0; og2 < OG / 2; og2++) {
        const int ogA = og2 * 2, ogB = ogA + 1;
        const uint4* pA = bfrag + ((size_t)(ogA * IN) * 32 + lane) * 2;
        const uint4* pB = bfrag + ((size_t)(ogB * IN) * 32 + lane) * 2;
        const int bcA = ogA * 8 + t4 * 2;
        const int bcB = ogB * 8 + t4 * 2;

        float accA0 = 0.f, accA1 = 0.f, accA2 = 0.f, accA3 = 0.f;
        float accB0 = 0.f, accB1 = 0.f, accB2 = 0.f, accB3 = 0.f;

        // prologue loads (i = 0)
        uint4 cA0 = pA[0], cA1 = pA[1];
        uint4 cB0 = pB[0], cB1 = pB[1];

#pragma unroll 2
        for (int i = 0; i < IN; i++) {
            // prefetch i+1 (stride per i = 64 uint4s)
            uint4 nA0, nA1, nB0, nB1;
            if (i + 1 < IN) {
                const uint4* qA = pA + (size_t)(i + 1) * 64;
                const uint4* qB = pB + (size_t)(i + 1) * 64;
                nA0 = qA[0]; nA1 = qA[1];
                nB0 = qB[0]; nB1 = qB[1];
            }

            float dA[4] = {0.f, 0.f, 0.f, 0.f};
            float dB[4] = {0.f, 0.f, 0.f, 0.f};
            mma_acc(dA, aF[0], cA0.x, cA0.y);
            mma_acc(dB, aF[0], cB0.x, cB0.y);
            mma_acc(dA, aF[1], cA0.z, cA0.w);
            mma_acc(dB, aF[1], cB0.z, cB0.w);
            mma_acc(dA, aF[2], cA1.x, cA1.y);
            mma_acc(dB, aF[2], cB1.x, cB1.y);
            mma_acc(dA, aF[3], cA1.z, cA1.w);
            mma_acc(dB, aF[3], cB1.z, cB1.w);

            float hv0 = h_s[i * 128 + row0];
            float hv1 = h_s[i * 128 + row1];
            float2 bbA = *(const float2*)&b2_s[i * OUT + bcA];
            float2 bbB = *(const float2*)&b2_s[i * OUT + bcB];

            accA0 += hv0 * leaky(dA[0] + bbA.x);
            accA1 += hv0 * leaky(dA[1] + bbA.y);
            accA2 += hv1 * leaky(dA[2] + bbA.x);
            accA3 += hv1 * leaky(dA[3] + bbA.y);
            accB0 += hv0 * leaky(dB[0] + bbB.x);
            accB1 += hv0 * leaky(dB[1] + bbB.y);
            accB2 += hv1 * leaky(dB[2] + bbB.x);
            accB3 += hv1 * leaky(dB[3] + bbB.y);

            cA0 = nA0; cA1 = nA1; cB0 = nB0; cB1 = nB1;
        }
        atomicAdd(&agg[d0n * OUT + bcA    ], accA0);
        atomicAdd(&agg[d0n * OUT + bcA + 1], accA1);
        atomicAdd(&agg[d1n * OUT + bcA    ], accA2);
        atomicAdd(&agg[d1n * OUT + bcA + 1], accA3);
        atomicAdd(&agg[d0n * OUT + bcB    ], accB0);
        atomicAdd(&agg[d0n * OUT + bcB + 1], accB1);
        atomicAdd(&agg[d1n * OUT + bcB    ], accB2);
        atomicAdd(&agg[d1n * OUT + bcB + 1], accB3);
    }
}

// ---------------- layer-1 specialized kernel (IN=4, OUT=8, fp32) ------------
// Block = 128 edges, 256 threads (2 threads per edge, 4 output cols each).
// Whole w2 (64x32 = 8 KB) staged once; no per-i syncs.
__global__ __launch_bounds__(256)
void edge_conv1_kernel(const float* __restrict__ x,
                       const int*   __restrict__ ei,
                       const float* __restrict__ w1,
                       const float* __restrict__ b1,
                       const float* __restrict__ w2,
                       const float* __restrict__ b2,
                       float*       __restrict__ agg)
{
    __shared__ float e_s[128 * 65];
    __shared__ float w2f[64 * 32];
    __shared__ float b2s[32];
    __shared__ float attr_s[128 * 3];
    __shared__ int   src_s[128], dst_s[128];

    const int tid = threadIdx.x;
    const int e0  = blockIdx.x * 128;

    for (int j = tid; j < 128; j += 256) {
        int s = ei[e0 + j];
        int d = ei[N_EDGES + e0 + j];
        src_s[j] = s; dst_s[j] = d;
        attr_s[j * 3 + 0] = x[d * 4 + 1] - x[s * 4 + 1];
        attr_s[j * 3 + 1] = x[d * 4 + 2] - x[s * 4 + 2];
        attr_s[j * 3 + 2] = x[d * 4 + 3] - x[s * 4 + 3];
    }
    for (int idx = tid; idx < 512; idx += 256)
        ((float4*)w2f)[idx] = ((const float4*)w2)[idx];
    if (tid < 32) b2s[tid] = b2[tid];
    __syncthreads();

    // edge hidden e = leaky(attr @ w1 + b1)
    for (int idx = tid; idx < 128 * 64; idx += 256) {
        int row = idx >> 6, k = idx & 63;
        float a0 = attr_s[row * 3], a1 = attr_s[row * 3 + 1], a2 = attr_s[row * 3 + 2];
        e_s[row * 65 + k] = leaky(b1[k] + a0 * w1[k] + a1 * w1[64 + k] + a2 * w1[128 + k]);
    }
    __syncthreads();

    const int row  = tid >> 1;
    const int bo   = (tid & 1) * 4;

    float c[4][4];
#pragma unroll
    for (int i = 0; i < 4; i++)
#pragma unroll
        for (int o = 0; o < 4; o++) c[i][o] = b2s[i * 8 + bo + o];

    const float* ep = e_s + row * 65;
    for (int k = 0; k < 64; k++) {
        float ev = ep[k];
#pragma unroll
        for (int i = 0; i < 4; i++) {
            float4 wv = *(const float4*)&w2f[k * 32 + i * 8 + bo];
            c[i][0] += ev * wv.x;
            c[i][1] += ev * wv.y;
            c[i][2] += ev * wv.z;
            c[i][3] += ev * wv.w;
        }
    }

    const float4 hx = *(const float4*)&x[src_s[row] * 4];
    float acc[4] = {0.f, 0.f, 0.f, 0.f};
#pragma unroll
    for (int i = 0; i < 4; i++) {
        float hv = (&hx.x)[i];
#pragma unroll
        for (int o = 0; o < 4; o++) acc[o] += hv * leaky(c[i][o]);
    }
    float* base = agg + dst_s[row] * 8 + bo;
#pragma unroll
    for (int o = 0; o < 4; o++) atomicAdd(base + o, acc[o]);
}

// ---------------- node update: h_next = leaky(agg + h @ root + cb) ---------
__global__ void node_update_kernel(const float* __restrict__ h,
                                   const float* __restrict__ agg,
                                   const float* __restrict__ root,
                                   const float* __restrict__ cb,
                                   float* __restrict__ out,
                                   int IN, int OUT)
{
    int gid = blockIdx.x * blockDim.x + threadIdx.x;
    if (gid >= N_NODES * OUT) return;
    int n = gid / OUT, o = gid % OUT;
    float t = agg[gid] + cb[o];
    for (int i = 0; i < IN; i++) t += h[n * IN + i] * root[i * OUT + o];
    out[gid] = leaky(t);
}

// ---------------- sum-pool over sorted batch_index --------------------------
#define POOL_CHUNK 50
__global__ void pool_kernel(const float* __restrict__ h3,
                            const int*   __restrict__ batch,
                            float*       __restrict__ g)
{
    int o  = threadIdx.x;
    int n0 = blockIdx.x * POOL_CHUNK;
    int n1 = n0 + POOL_CHUNK; if (n1 > N_NODES) n1 = N_NODES;
    float s = 0.f;
    int cur = batch[n0];
    for (int n = n0; n < n1; n++) {
        int b = batch[n];
        if (b != cur) { atomicAdd(&g[cur * 128 + o], s); s = 0.f; cur = b; }
        s += h3[n * 128 + o];
    }
    atomicAdd(&g[cur * 128 + o], s);
}

// ---------------- readout MLP: 128->128->64->1 ------------------------------
__global__ void readout_kernel(const float* __restrict__ g,
                               const float* __restrict__ w1, const float* __restrict__ b1,
                               const float* __restrict__ w2, const float* __restrict__ b2,
                               const float* __restrict__ w3, const float* __restrict__ b3,
                               float* __restrict__ out)
{
    __shared__ float gin[128], g1[128], g2[64];
    int b = blockIdx.x, t = threadIdx.x;
    gin[t] = g[b * 128 + t];
    __syncthreads();
    float s = b1[t];
    for (int i = 0; i < 128; i++) s += gin[i] * w1[i * 128 + t];
    g1[t] = leaky(s);
    __syncthreads();
    if (t < 64) {
        float s2 = b2[t];
        for (int i = 0; i < 128; i++) s2 += g1[i] * w2[i * 64 + t];
        g2[t] = leaky(s2);
    }
    __syncthreads();
    if (t < 64) g1[t] = g2[t] * w3[t];
    __syncthreads();
    if (t == 0) {
        float s3 = b3[0];
        for (int i = 0; i < 64; i++) s3 += g1[i];
        out[b] = s3;
    }
}

// ---------------- launch ----------------------------------------------------
static constexpr int smem_mma(int IN, int OUT) {
    return 4 * (128 * 33 + IN * 128 + IN * OUT + 384 + 256);
}

extern "C" void kernel_launch(void* const* d_in, const int* in_sizes, int n_in,
                              void* d_out, int out_size)
{
    const float* x       = (const float*)d_in[0];
    const int*   ei      = (const int*)  d_in[1];
    const int*   batch   = (const int*)  d_in[2];
    const float* en1_w1  = (const float*)d_in[3];
    const float* en1_b1  = (const float*)d_in[4];
    const float* en1_w2  = (const float*)d_in[5];
    const float* en1_b2  = (const float*)d_in[6];
    const float* en2_w1  = (const float*)d_in[7];
    const float* en2_b1  = (const float*)d_in[8];
    const float* en2_w2  = (const float*)d_in[9];
    const float* en2_b2  = (const float*)d_in[10];
    const float* en3_w1  = (const float*)d_in[11];
    const float* en3_b1  = (const float*)d_in[12];
    const float* en3_w2  = (const float*)d_in[13];
    const float* en3_b2  = (const float*)d_in[14];
    const float* root1   = (const float*)d_in[15];
    const float* cb1     = (const float*)d_in[16];
    const float* root2   = (const float*)d_in[17];
    const float* cb2     = (const float*)d_in[18];
    const float* root3   = (const float*)d_in[19];
    const float* cb3     = (const float*)d_in[20];
    const float* fc1_w   = (const float*)d_in[21];
    const float* fc1_b   = (const float*)d_in[22];
    const float* fc2_w   = (const float*)d_in[23];
    const float* fc2_b   = (const float*)d_in[24];
    const float* fc3_w   = (const float*)d_in[25];
    const float* fc3_b   = (const float*)d_in[26];

    float *h1, *h2, *h3, *agg, *gp;
    uint4 *bf3, *bf2;
    cudaGetSymbolAddress((void**)&h1,  g_h1);
    cudaGetSymbolAddress((void**)&h2,  g_h2);
    cudaGetSymbolAddress((void**)&h3,  g_h3);
    cudaGetSymbolAddress((void**)&agg, g_agg);
    cudaGetSymbolAddress((void**)&gp,  g_pool);
    cudaGetSymbolAddress((void**)&bf3, g_bf_l3);
    cudaGetSymbolAddress((void**)&bf2, g_bf_l2);

    constexpr int SM2 = smem_mma(8, 64);
    constexpr int SM3 = smem_mma(64, 128);
    cudaFuncSetAttribute(edge_conv_mma<64, 128>,
                         cudaFuncAttributeMaxDynamicSharedMemorySize, SM3);
    cudaFuncSetAttribute(edge_conv_mma<8, 64>,
                         cudaFuncAttributeMaxDynamicSharedMemorySize, SM2);

    // ---- prep: rearrange w2 of layers 2 & 3 into bf16 mma fragments
    prep_w2_frag<<<(16 * 64 * 64 + 255) / 256, 256>>>(en3_w2, bf3, 64, 128, 16 * 64 * 64);
    prep_w2_frag<<<(8 * 8 * 64 + 255) / 256, 256>>>(en2_w2, bf2, 8, 64, 8 * 8 * 64);

    // ---- layer 1: in=4, out=8 (specialized fp32)
    zero_kernel<<<(N_NODES * 8 + 255) / 256, 256>>>(agg, N_NODES * 8);
    edge_conv1_kernel<<<N_EDGES / 128, 256>>>(x, ei, en1_w1, en1_b1, en1_w2, en1_b2, agg);
    node_update_kernel<<<(N_NODES * 8 + 255) / 256, 256>>>(x, agg, root1, cb1, h1, 4, 8);

    // ---- layer 2: in=8, out=64 (bf16 mma)
    zero_kernel<<<(N_NODES * 64 + 255) / 256, 256>>>(agg, N_NODES * 64);
    edge_conv_mma<8, 64><<<N_EDGES / 128, 256, SM2>>>(
        x, h1, ei, en2_w1, en2_b1, bf2, en2_b2, agg);
    node_update_kernel<<<(N_NODES * 64 + 255) / 256, 256>>>(h1, agg, root2, cb2, h2, 8, 64);

    // ---- layer 3: in=64, out=128 (bf16 mma)
    zero_kernel<<<(N_NODES * 128 + 255) / 256, 256>>>(agg, N_NODES * 128);
    edge_conv_mma<64, 128><<<N_EDGES / 128, 256, SM3>>>(
        x, h2, ei, en3_w1, en3_b1, bf3, en3_b2, agg);
    node_update_kernel<<<(N_NODES * 128 + 255) / 256, 256>>>(h2, agg, root3, cb3, h3, 64, 128);

    // ---- pool + readout
    zero_kernel<<<(N_GRAPHS * 128 + 255) / 256, 256>>>(gp, N_GRAPHS * 128);
    pool_kernel<<<(N_NODES + POOL_CHUNK - 1) / POOL_CHUNK, 128>>>(h3, batch, gp);
    readout_kernel<<<N_GRAPHS, 128>>>(gp, fc1_w, fc1_b, fc2_w, fc2_b, fc3_w, fc3_b,
                                      (float*)d_out);
}

// round 9
// speedup vs baseline: 5.4090x; 1.0737x over previous
#include <cuda_runtime.h>
#include <cuda_bf16.h>
#include <cstdint>

#define N_NODES  8000
#define N_EDGES  32000
#define N_GRAPHS 32

// ---------------- scratch (device globals; no allocations anywhere) --------
__device__ float g_h1[N_NODES * 8];
__device__ float g_h2[N_NODES * 64];
__device__ float g_h3[N_NODES * 128];
__device__ float g_agg[N_NODES * 128];
__device__ float g_pool[N_GRAPHS * 128];
// bf16 B-fragments of w2, per-lane contiguous layout:
// uint4 index = ((og*IN + i)*32 + lane)*2 + q
//   q=0: {kt0.b0, kt0.b1, kt1.b0, kt1.b1}, q=1: {kt2.., kt3..}
__device__ uint4 g_bf_l3[16 * 64 * 32 * 2];
__device__ uint4 g_bf_l2[8 * 8 * 32 * 2];

__device__ __forceinline__ float leaky(float v) { return v > 0.f ? v : 0.1f * v; }

__device__ __forceinline__ uint32_t pack_bf2(float x, float y) {
    __nv_bfloat16 bx = __float2bfloat16(x);
    __nv_bfloat16 by = __float2bfloat16(y);
    uint16_t ux = *(uint16_t*)&bx, uy = *(uint16_t*)&by;
    return (uint32_t)ux | ((uint32_t)uy << 16);
}

// mma.sync m16n8k16 row.col f32 += bf16*bf16 (accumulate in place)
__device__ __forceinline__ void mma_acc(float* d, const uint32_t* a,
                                        uint32_t b0, uint32_t b1) {
    asm volatile(
        "mma.sync.aligned.m16n8k16.row.col.f32.bf16.bf16.f32 "
        "{%0,%1,%2,%3}, {%4,%5,%6,%7}, {%8,%9}, {%0,%1,%2,%3};"
        : "+f"(d[0]), "+f"(d[1]), "+f"(d[2]), "+f"(d[3])
        : "r"(a[0]), "r"(a[1]), "r"(a[2]), "r"(a[3]), "r"(b0), "r"(b1));
}

// ---------------- utility: zero a buffer -----------------------------------
__global__ void zero_kernel(float* __restrict__ p, int n) {
    int i = blockIdx.x * blockDim.x + threadIdx.x;
    if (i < n) p[i] = 0.f;
}

// ---------------- prep: w2 [64, IN*OUT] -> bf16 B fragments -----------------
__global__ void prep_w2_frag(const float* __restrict__ w2,
                             uint4* __restrict__ frag,
                             int IN, int OUT, int total)
{
    int idx = blockIdx.x * blockDim.x + threadIdx.x;
    if (idx >= total) return;
    int q    = idx & 1;
    int lane = (idx >> 1) & 31;
    int i    = (idx >> 6) % IN;
    int og   = idx / (IN * 64);
    int t4 = lane & 3, g = lane >> 2;
    int ncols = IN * OUT;
    int col = i * OUT + og * 8 + g;

    uint32_t r[4];
#pragma unroll
    for (int kk = 0; kk < 2; kk++) {
        int kt = q * 2 + kk;
        int k0 = kt * 16 + t4 * 2;
        r[kk * 2 + 0] = pack_bf2(w2[(k0    ) * ncols + col], w2[(k0 + 1) * ncols + col]);
        r[kk * 2 + 1] = pack_bf2(w2[(k0 + 8) * ncols + col], w2[(k0 + 9) * ncols + col]);
    }
    frag[idx] = make_uint4(r[0], r[1], r[2], r[3]);
}

// ---------------- fused NNConv via bf16 mma.sync (layers 2 & 3) -------------
// Block = 128 edges, 128 threads = 4 warps, 32 edges/warp (TWO M16 tiles).
// One B-fragment load feeds both A tiles -> B L2 traffic halved vs round 8.
// Per i: 16 MMAs in 4 independent chains; B software-pipelined.
template <int IN, int OUT>
__global__ __launch_bounds__(128)
void edge_conv_mma(const float* __restrict__ x,
                   const float* __restrict__ h,
                   const int*   __restrict__ ei,
                   const float* __restrict__ w1,
                   const float* __restrict__ b1,
                   const uint4* __restrict__ bfrag,
                   const float* __restrict__ b2,
                   float*       __restrict__ agg)
{
    constexpr int OG = OUT / 8;
    constexpr int W_EHI  = 0;                    // 128 x 33 bf16x2 words
    constexpr int W_H    = W_EHI + 128 * 33;     // IN x 128 fp32
    constexpr int W_B2   = W_H + IN * 128;       // IN*OUT fp32
    constexpr int W_ATTR = W_B2 + IN * OUT;      // 384
    constexpr int W_SRC  = W_ATTR + 384;
    constexpr int W_DST  = W_SRC + 128;

    extern __shared__ uint32_t sm[];
    uint32_t* e_hi   = sm + W_EHI;
    float*    h_s    = (float*)(sm + W_H);
    float*    b2_s   = (float*)(sm + W_B2);
    float*    attr_s = (float*)(sm + W_ATTR);
    int*      src_s  = (int*)(sm + W_SRC);
    int*      dst_s  = (int*)(sm + W_DST);

    const int tid = threadIdx.x;
    const int e0  = blockIdx.x * 128;

    // --- edge indices + relative-position attrs
    for (int j = tid; j < 128; j += 128) {
        int s = ei[e0 + j];
        int d = ei[N_EDGES + e0 + j];
        src_s[j] = s; dst_s[j] = d;
        attr_s[j * 3 + 0] = x[d * 4 + 1] - x[s * 4 + 1];
        attr_s[j * 3 + 1] = x[d * 4 + 2] - x[s * 4 + 2];
        attr_s[j * 3 + 2] = x[d * 4 + 3] - x[s * 4 + 3];
    }
    // --- stage b2
    for (int idx = tid; idx < IN * OUT / 4; idx += 128)
        ((float4*)b2_s)[idx] = ((const float4*)b2)[idx];
    __syncthreads();

    // --- edge hidden e = leaky(attr @ w1 + b1), packed bf16x2
    for (int idx = tid; idx < 4096; idx += 128) {
        int row = idx >> 5, cp = idx & 31;
        float a0 = attr_s[row * 3], a1 = attr_s[row * 3 + 1], a2 = attr_s[row * 3 + 2];
        int c0 = cp * 2, c1 = c0 + 1;
        float v0 = leaky(b1[c0] + a0 * w1[c0] + a1 * w1[64 + c0] + a2 * w1[128 + c0]);
        float v1 = leaky(b1[c1] + a0 * w1[c1] + a1 * w1[64 + c1] + a2 * w1[128 + c1]);
        e_hi[row * 33 + cp] = pack_bf2(v0, v1);
    }
    // --- h[src] gathered transposed: h_s[i*128 + j]
    for (int idx = tid; idx < 128 * (IN / 4); idx += 128) {
        int j = idx & 127, q = idx >> 7;
        float4 v = ((const float4*)(h + src_s[j] * IN))[q];
        h_s[(4 * q + 0) * 128 + j] = v.x;
        h_s[(4 * q + 1) * 128 + j] = v.y;
        h_s[(4 * q + 2) * 128 + j] = v.z;
        h_s[(4 * q + 3) * 128 + j] = v.w;
    }
    __syncthreads();

    const int lane = tid & 31, w = tid >> 5;
    const int g = lane >> 2, t4 = lane & 3;
    const int r0 = w * 32 + g;            // tile0 rows: r0, r0+8
    const int r2 = r0 + 16;               // tile1 rows: r2, r2+8

    // --- A fragments for both tiles (built once)
    uint32_t aF0[4][4], aF1[4][4];
#pragma unroll
    for (int kt = 0; kt < 4; kt++) {
        int cp = kt * 8 + t4;
        aF0[kt][0] = e_hi[(r0    ) * 33 + cp];
        aF0[kt][1] = e_hi[(r0 + 8) * 33 + cp];
        aF0[kt][2] = e_hi[(r0    ) * 33 + cp + 4];
        aF0[kt][3] = e_hi[(r0 + 8) * 33 + cp + 4];
        aF1[kt][0] = e_hi[(r2    ) * 33 + cp];
        aF1[kt][1] = e_hi[(r2 + 8) * 33 + cp];
        aF1[kt][2] = e_hi[(r2    ) * 33 + cp + 4];
        aF1[kt][3] = e_hi[(r2 + 8) * 33 + cp + 4];
    }

    const int d0n = dst_s[r0], d1n = dst_s[r0 + 8];
    const int d2n = dst_s[r2], d3n = dst_s[r2 + 8];

    for (int og2 = 0; og2 < OG / 2; og2++) {
        const int ogA = og2 * 2, ogB = ogA + 1;
        const uint4* pA = bfrag + ((size_t)(ogA * IN) * 32 + lane) * 2;
        const uint4* pB = bfrag + ((size_t)(ogB * IN) * 32 + lane) * 2;
        const int bcA = ogA * 8 + t4 * 2;
        const int bcB = ogB * 8 + t4 * 2;

        float acA0[4] = {0,0,0,0}, acB0[4] = {0,0,0,0};   // tile0: [row0, row0; row1, row1] pairs
        float acA1[4] = {0,0,0,0}, acB1[4] = {0,0,0,0};   // tile1

        // prologue loads (i = 0)
        uint4 cA0 = pA[0], cA1 = pA[1];
        uint4 cB0 = pB[0], cB1 = pB[1];

#pragma unroll 2
        for (int i = 0; i < IN; i++) {
            uint4 nA0, nA1, nB0, nB1;
            if (i + 1 < IN) {
                const uint4* qA = pA + (size_t)(i + 1) * 64;
                const uint4* qB = pB + (size_t)(i + 1) * 64;
                nA0 = qA[0]; nA1 = qA[1];
                nB0 = qB[0]; nB1 = qB[1];
            }

            float dA0[4] = {0,0,0,0}, dB0[4] = {0,0,0,0};
            float dA1[4] = {0,0,0,0}, dB1[4] = {0,0,0,0};
            // 4 independent chains of 4, interleaved
            mma_acc(dA0, aF0[0], cA0.x, cA0.y);
            mma_acc(dB0, aF0[0], cB0.x, cB0.y);
            mma_acc(dA1, aF1[0], cA0.x, cA0.y);
            mma_acc(dB1, aF1[0], cB0.x, cB0.y);
            mma_acc(dA0, aF0[1], cA0.z, cA0.w);
            mma_acc(dB0, aF0[1], cB0.z, cB0.w);
            mma_acc(dA1, aF1[1], cA0.z, cA0.w);
            mma_acc(dB1, aF1[1], cB0.z, cB0.w);
            mma_acc(dA0, aF0[2], cA1.x, cA1.y);
            mma_acc(dB0, aF0[2], cB1.x, cB1.y);
            mma_acc(dA1, aF1[2], cA1.x, cA1.y);
            mma_acc(dB1, aF1[2], cB1.x, cB1.y);
            mma_acc(dA0, aF0[3], cA1.z, cA1.w);
            mma_acc(dB0, aF0[3], cB1.z, cB1.w);
            mma_acc(dA1, aF1[3], cA1.z, cA1.w);
            mma_acc(dB1, aF1[3], cB1.z, cB1.w);

            float hv0 = h_s[i * 128 + r0];
            float hv1 = h_s[i * 128 + r0 + 8];
            float hv2 = h_s[i * 128 + r2];
            float hv3 = h_s[i * 128 + r2 + 8];
            float2 bbA = *(const float2*)&b2_s[i * OUT + bcA];
            float2 bbB = *(const float2*)&b2_s[i * OUT + bcB];

            acA0[0] += hv0 * leaky(dA0[0] + bbA.x);
            acA0[1] += hv0 * leaky(dA0[1] + bbA.y);
            acA0[2] += hv1 * leaky(dA0[2] + bbA.x);
            acA0[3] += hv1 * leaky(dA0[3] + bbA.y);
            acB0[0] += hv0 * leaky(dB0[0] + bbB.x);
            acB0[1] += hv0 * leaky(dB0[1] + bbB.y);
            acB0[2] += hv1 * leaky(dB0[2] + bbB.x);
            acB0[3] += hv1 * leaky(dB0[3] + bbB.y);
            acA1[0] += hv2 * leaky(dA1[0] + bbA.x);
            acA1[1] += hv2 * leaky(dA1[1] + bbA.y);
            acA1[2] += hv3 * leaky(dA1[2] + bbA.x);
            acA1[3] += hv3 * leaky(dA1[3] + bbA.y);
            acB1[0] += hv2 * leaky(dB1[0] + bbB.x);
            acB1[1] += hv2 * leaky(dB1[1] + bbB.y);
            acB1[2] += hv3 * leaky(dB1[2] + bbB.x);
            acB1[3] += hv3 * leaky(dB1[3] + bbB.y);

            cA0 = nA0; cA1 = nA1; cB0 = nB0; cB1 = nB1;
        }
        atomicAdd(&agg[d0n * OUT + bcA    ], acA0[0]);
        atomicAdd(&agg[d0n * OUT + bcA + 1], acA0[1]);
        atomicAdd(&agg[d1n * OUT + bcA    ], acA0[2]);
        atomicAdd(&agg[d1n * OUT + bcA + 1], acA0[3]);
        atomicAdd(&agg[d0n * OUT + bcB    ], acB0[0]);
        atomicAdd(&agg[d0n * OUT + bcB + 1], acB0[1]);
        atomicAdd(&agg[d1n * OUT + bcB    ], acB0[2]);
        atomicAdd(&agg[d1n * OUT + bcB + 1], acB0[3]);
        atomicAdd(&agg[d2n * OUT + bcA    ], acA1[0]);
        atomicAdd(&agg[d2n * OUT + bcA + 1], acA1[1]);
        atomicAdd(&agg[d3n * OUT + bcA    ], acA1[2]);
        atomicAdd(&agg[d3n * OUT + bcA + 1], acA1[3]);
        atomicAdd(&agg[d2n * OUT + bcB    ], acB1[0]);
        atomicAdd(&agg[d2n * OUT + bcB + 1], acB1[1]);
        atomicAdd(&agg[d3n * OUT + bcB    ], acB1[2]);
        atomicAdd(&agg[d3n * OUT + bcB + 1], acB1[3]);
    }
}

// ---------------- layer-1 specialized kernel (IN=4, OUT=8, fp32) ------------
// Block = 64 edges, 128 threads (2 threads/edge); grid 500 fills the chip.
__global__ __launch_bounds__(128)
void edge_conv1_kernel(const float* __restrict__ x,
                       const int*   __restrict__ ei,
                       const float* __restrict__ w1,
                       const float* __restrict__ b1,
                       const float* __restrict__ w2,
                       const float* __restrict__ b2,
                       float*       __restrict__ agg)
{
    __shared__ float e_s[64 * 65];
    __shared__ float w2f[64 * 32];
    __shared__ float b2s[32];
    __shared__ float attr_s[64 * 3];
    __shared__ int   src_s[64], dst_s[64];

    const int tid = threadIdx.x;
    const int e0  = blockIdx.x * 64;

    if (tid < 64) {
        int j = tid;
        int s = ei[e0 + j];
        int d = ei[N_EDGES + e0 + j];
        src_s[j] = s; dst_s[j] = d;
        attr_s[j * 3 + 0] = x[d * 4 + 1] - x[s * 4 + 1];
        attr_s[j * 3 + 1] = x[d * 4 + 2] - x[s * 4 + 2];
        attr_s[j * 3 + 2] = x[d * 4 + 3] - x[s * 4 + 3];
    }
    for (int idx = tid; idx < 512; idx += 128)
        ((float4*)w2f)[idx] = ((const float4*)w2)[idx];
    if (tid < 32) b2s[tid] = b2[tid];
    __syncthreads();

    // edge hidden e = leaky(attr @ w1 + b1)
    for (int idx = tid; idx < 64 * 64; idx += 128) {
        int row = idx >> 6, k = idx & 63;
        float a0 = attr_s[row * 3], a1 = attr_s[row * 3 + 1], a2 = attr_s[row * 3 + 2];
        e_s[row * 65 + k] = leaky(b1[k] + a0 * w1[k] + a1 * w1[64 + k] + a2 * w1[128 + k]);
    }
    __syncthreads();

    const int row = tid >> 1;
    const int bo  = (tid & 1) * 4;

    float c[4][4];
#pragma unroll
    for (int i = 0; i < 4; i++)
#pragma unroll
        for (int o = 0; o < 4; o++) c[i][o] = b2s[i * 8 + bo + o];

    const float* ep = e_s + row * 65;
    for (int k = 0; k < 64; k++) {
        float ev = ep[k];
#pragma unroll
        for (int i = 0; i < 4; i++) {
            float4 wv = *(const float4*)&w2f[k * 32 + i * 8 + bo];
            c[i][0] += ev * wv.x;
            c[i][1] += ev * wv.y;
            c[i][2] += ev * wv.z;
            c[i][3] += ev * wv.w;
        }
    }

    const float4 hx = *(const float4*)&x[src_s[row] * 4];
    float acc[4] = {0.f, 0.f, 0.f, 0.f};
#pragma unroll
    for (int i = 0; i < 4; i++) {
        float hv = (&hx.x)[i];
#pragma unroll
        for (int o = 0; o < 4; o++) acc[o] += hv * leaky(c[i][o]);
    }
    float* base = agg + dst_s[row] * 8 + bo;
#pragma unroll
    for (int o = 0; o < 4; o++) atomicAdd(base + o, acc[o]);
}

// ---------------- node update: h_next = leaky(agg + h @ root + cb) ---------
__global__ void node_update_kernel(const float* __restrict__ h,
                                   const float* __restrict__ agg,
                                   const float* __restrict__ root,
                                   const float* __restrict__ cb,
                                   float* __restrict__ out,
                                   int IN, int OUT)
{
    int gid = blockIdx.x * blockDim.x + threadIdx.x;
    if (gid >= N_NODES * OUT) return;
    int n = gid / OUT, o = gid % OUT;
    float t = agg[gid] + cb[o];
    for (int i = 0; i < IN; i++) t += h[n * IN + i] * root[i * OUT + o];
    out[gid] = leaky(t);
}

// ---------------- sum-pool over sorted batch_index --------------------------
#define POOL_CHUNK 50
__global__ void pool_kernel(const float* __restrict__ h3,
                            const int*   __restrict__ batch,
                            float*       __restrict__ g)
{
    int o  = threadIdx.x;
    int n0 = blockIdx.x * POOL_CHUNK;
    int n1 = n0 + POOL_CHUNK; if (n1 > N_NODES) n1 = N_NODES;
    float s = 0.f;
    int cur = batch[n0];
    for (int n = n0; n < n1; n++) {
        int b = batch[n];
        if (b != cur) { atomicAdd(&g[cur * 128 + o], s); s = 0.f; cur = b; }
        s += h3[n * 128 + o];
    }
    atomicAdd(&g[cur * 128 + o], s);
}

// ---------------- readout MLP: 128->128->64->1 ------------------------------
__global__ void readout_kernel(const float* __restrict__ g,
                               const float* __restrict__ w1, const float* __restrict__ b1,
                               const float* __restrict__ w2, const float* __restrict__ b2,
                               const float* __restrict__ w3, const float* __restrict__ b3,
                               float* __restrict__ out)
{
    __shared__ float gin[128], g1[128], g2[64];
    int b = blockIdx.x, t = threadIdx.x;
    gin[t] = g[b * 128 + t];
    __syncthreads();
    float s = b1[t];
    for (int i = 0; i < 128; i++) s += gin[i] * w1[i * 128 + t];
    g1[t] = leaky(s);
    __syncthreads();
    if (t < 64) {
        float s2 = b2[t];
        for (int i = 0; i < 128; i++) s2 += g1[i] * w2[i * 64 + t];
        g2[t] = leaky(s2);
    }
    __syncthreads();
    if (t < 64) g1[t] = g2[t] * w3[t];
    __syncthreads();
    if (t == 0) {
        float s3 = b3[0];
        for (int i = 0; i < 64; i++) s3 += g1[i];
        out[b] = s3;
    }
}

// ---------------- launch ----------------------------------------------------
static constexpr int smem_mma(int IN, int OUT) {
    return 4 * (128 * 33 + IN * 128 + IN * OUT + 384 + 256);
}

extern "C" void kernel_launch(void* const* d_in, const int* in_sizes, int n_in,
                              void* d_out, int out_size)
{
    const float* x       = (const float*)d_in[0];
    const int*   ei      = (const int*)  d_in[1];
    const int*   batch   = (const int*)  d_in[2];
    const float* en1_w1  = (const float*)d_in[3];
    const float* en1_b1  = (const float*)d_in[4];
    const float* en1_w2  = (const float*)d_in[5];
    const float* en1_b2  = (const float*)d_in[6];
    const float* en2_w1  = (const float*)d_in[7];
    const float* en2_b1  = (const float*)d_in[8];
    const float* en2_w2  = (const float*)d_in[9];
    const float* en2_b2  = (const float*)d_in[10];
    const float* en3_w1  = (const float*)d_in[11];
    const float* en3_b1  = (const float*)d_in[12];
    const float* en3_w2  = (const float*)d_in[13];
    const float* en3_b2  = (const float*)d_in[14];
    const float* root1   = (const float*)d_in[15];
    const float* cb1     = (const float*)d_in[16];
    const float* root2   = (const float*)d_in[17];
    const float* cb2     = (const float*)d_in[18];
    const float* root3   = (const float*)d_in[19];
    const float* cb3     = (const float*)d_in[20];
    const float* fc1_w   = (const float*)d_in[21];
    const float* fc1_b   = (const float*)d_in[22];
    const float* fc2_w   = (const float*)d_in[23];
    const float* fc2_b   = (const float*)d_in[24];
    const float* fc3_w   = (const float*)d_in[25];
    const float* fc3_b   = (const float*)d_in[26];

    float *h1, *h2, *h3, *agg, *gp;
    uint4 *bf3, *bf2;
    cudaGetSymbolAddress((void**)&h1,  g_h1);
    cudaGetSymbolAddress((void**)&h2,  g_h2);
    cudaGetSymbolAddress((void**)&h3,  g_h3);
    cudaGetSymbolAddress((void**)&agg, g_agg);
    cudaGetSymbolAddress((void**)&gp,  g_pool);
    cudaGetSymbolAddress((void**)&bf3, g_bf_l3);
    cudaGetSymbolAddress((void**)&bf2, g_bf_l2);

    constexpr int SM2 = smem_mma(8, 64);
    constexpr int SM3 = smem_mma(64, 128);
    cudaFuncSetAttribute(edge_conv_mma<64, 128>,
                         cudaFuncAttributeMaxDynamicSharedMemorySize, SM3);
    cudaFuncSetAttribute(edge_conv_mma<8, 64>,
                         cudaFuncAttributeMaxDynamicSharedMemorySize, SM2);

    // ---- prep: rearrange w2 of layers 2 & 3 into bf16 mma fragments
    prep_w2_frag<<<(16 * 64 * 64 + 255) / 256, 256>>>(en3_w2, bf3, 64, 128, 16 * 64 * 64);
    prep_w2_frag<<<(8 * 8 * 64 + 255) / 256, 256>>>(en2_w2, bf2, 8, 64, 8 * 8 * 64);

    // ---- layer 1: in=4, out=8 (specialized fp32)
    zero_kernel<<<(N_NODES * 8 + 255) / 256, 256>>>(agg, N_NODES * 8);
    edge_conv1_kernel<<<N_EDGES / 64, 128>>>(x, ei, en1_w1, en1_b1, en1_w2, en1_b2, agg);
    node_update_kernel<<<(N_NODES * 8 + 255) / 256, 256>>>(x, agg, root1, cb1, h1, 4, 8);

    // ---- layer 2: in=8, out=64 (bf16 mma, 2 tiles/warp)
    zero_kernel<<<(N_NODES * 64 + 255) / 256, 256>>>(agg, N_NODES * 64);
    edge_conv_mma<8, 64><<<N_EDGES / 128, 128, SM2>>>(
        x, h1, ei, en2_w1, en2_b1, bf2, en2_b2, agg);
    node_update_kernel<<<(N_NODES * 64 + 255) / 256, 256>>>(h1, agg, root2, cb2, h2, 8, 64);

    // ---- layer 3: in=64, out=128 (bf16 mma, 2 tiles/warp)
    zero_kernel<<<(N_NODES * 128 + 255) / 256, 256>>>(agg, N_NODES * 128);
    edge_conv_mma<64, 128><<<N_EDGES / 128, 128, SM3>>>(
        x, h2, ei, en3_w1, en3_b1, bf3, en3_b2, agg);
    node_update_kernel<<<(N_NODES * 128 + 255) / 256, 256>>>(h2, agg, root3, cb3, h3, 64, 128);

    // ---- pool + readout
    zero_kernel<<<(N_GRAPHS * 128 + 255) / 256, 256>>>(gp, N_GRAPHS * 128);
    pool_kernel<<<(N_NODES + POOL_CHUNK - 1) / POOL_CHUNK, 128>>>(h3, batch, gp);
    readout_kernel<<<N_GRAPHS, 128>>>(gp, fc1_w, fc1_b, fc2_w, fc2_b, fc3_w, fc3_b,
                                      (float*)d_out);
}